// round 6
// baseline (speedup 1.0000x reference)
#include <cuda_runtime.h>
#include <mma.h>
#include <math.h>
using namespace nvcuda;

#define NMAX 50000
#define EMAX 800000
#define NP   50048   // 391*128, padded rows so wmma stores need no guard
#define SB   512     // scan block size

// ---------------- scratch (device globals; no allocation allowed) ------------
__device__ float d_h1[NP * 256];     // layer1 transformed features (padded)
__device__ float d_al1[NMAX * 4];
__device__ float d_ar1[NMAX * 4];
__device__ float d_g1[NMAX];
__device__ float d_x2[NMAX * 256];   // elu(normalized aggregate) = GEMM2 input
__device__ float d_h2[NP * 64];      // layer2 transformed features (padded)
__device__ float d_al2[NMAX];
__device__ float d_ar2[NMAX];
__device__ float d_g2[NMAX];
// CSR (edges sorted by destination)
__device__ int   d_deg[NMAX];
__device__ int   d_cur[NMAX];
__device__ int   d_rs[NMAX + 1];
__device__ int   d_bt[(NMAX + SB - 1) / SB];
__device__ int   d_srcs[EMAX];

__device__ __forceinline__ float elu_f(float v) {
    return v > 0.f ? v : (__expf(v) - 1.0f);
}
__device__ __forceinline__ float to_tf32(float x) {
    float r;
    asm("cvt.rna.tf32.f32 %0, %1;" : "=f"(r) : "f"(x));
    return r;
}

// ---------------- split-TF32 tensor-core GEMM: C[N,M] = A[N,K] @ B[K,M] -------
// Split ONCE at smem-load time: a = a_hi + a_lo (each tf32-valued fp32).
// Inner loop: pure fragment loads + 3 MMAs (hi*hi, hi*lo, lo*hi), fp32 accum.
// Block tile 128x64, BK=16, 256 thr = 8 warps (4x2), warp tile 32x32.
__global__ __launch_bounds__(256) void gemm_tf32x3(
        const float* __restrict__ A, const float* __restrict__ B,
        float* __restrict__ C, int N, int K, int M) {
    __shared__ float AsH[128][24], AsL[128][24];
    __shared__ float BsH[16][72],  BsL[16][72];
    int tid = threadIdx.x;
    int wid = tid >> 5;
    int wm = wid >> 1, wn = wid & 1;
    int row0 = blockIdx.y * 128, col0 = blockIdx.x * 64;

    wmma::fragment<wmma::accumulator, 16, 16, 8, float> acc[2][2];
    #pragma unroll
    for (int i = 0; i < 2; i++)
        #pragma unroll
        for (int j = 0; j < 2; j++)
            wmma::fill_fragment(acc[i][j], 0.0f);

    for (int k0 = 0; k0 < K; k0 += 16) {
        // A tile 128x16: 512 float4, 2 per thread; split hi/lo at load
        #pragma unroll
        for (int i = 0; i < 2; i++) {
            int f = tid + i * 256;
            int r = f >> 2, c = (f & 3) * 4;
            int row = row0 + r;
            float4 v = make_float4(0.f, 0.f, 0.f, 0.f);
            if (row < N) v = *(const float4*)&A[(size_t)row * K + k0 + c];
            float4 h, l;
            h.x = to_tf32(v.x); l.x = to_tf32(v.x - h.x);
            h.y = to_tf32(v.y); l.y = to_tf32(v.y - h.y);
            h.z = to_tf32(v.z); l.z = to_tf32(v.z - h.z);
            h.w = to_tf32(v.w); l.w = to_tf32(v.w - h.w);
            *(float4*)&AsH[r][c] = h;
            *(float4*)&AsL[r][c] = l;
        }
        // B tile 16x64: 256 float4, 1 per thread; split hi/lo at load
        {
            int r = tid >> 4, c = (tid & 15) * 4;
            float4 v = *(const float4*)&B[(size_t)(k0 + r) * M + col0 + c];
            float4 h, l;
            h.x = to_tf32(v.x); l.x = to_tf32(v.x - h.x);
            h.y = to_tf32(v.y); l.y = to_tf32(v.y - h.y);
            h.z = to_tf32(v.z); l.z = to_tf32(v.z - h.z);
            h.w = to_tf32(v.w); l.w = to_tf32(v.w - h.w);
            *(float4*)&BsH[r][c] = h;
            *(float4*)&BsL[r][c] = l;
        }
        __syncthreads();

        #pragma unroll
        for (int kk = 0; kk < 2; kk++) {
            wmma::fragment<wmma::matrix_a, 16, 16, 8, wmma::precision::tf32, wmma::row_major> ahi[2], alo[2];
            wmma::fragment<wmma::matrix_b, 16, 16, 8, wmma::precision::tf32, wmma::row_major> bhi[2], blo[2];
            #pragma unroll
            for (int i = 0; i < 2; i++) {
                wmma::load_matrix_sync(ahi[i], &AsH[wm * 32 + i * 16][kk * 8], 24);
                wmma::load_matrix_sync(alo[i], &AsL[wm * 32 + i * 16][kk * 8], 24);
            }
            #pragma unroll
            for (int j = 0; j < 2; j++) {
                wmma::load_matrix_sync(bhi[j], &BsH[kk * 8][wn * 32 + j * 16], 72);
                wmma::load_matrix_sync(blo[j], &BsL[kk * 8][wn * 32 + j * 16], 72);
            }
            #pragma unroll
            for (int i = 0; i < 2; i++)
                #pragma unroll
                for (int j = 0; j < 2; j++) {
                    wmma::mma_sync(acc[i][j], alo[i], bhi[j], acc[i][j]);
                    wmma::mma_sync(acc[i][j], ahi[i], blo[j], acc[i][j]);
                    wmma::mma_sync(acc[i][j], ahi[i], bhi[j], acc[i][j]);
                }
        }
        __syncthreads();
    }
    #pragma unroll
    for (int i = 0; i < 2; i++)
        #pragma unroll
        for (int j = 0; j < 2; j++)
            wmma::store_matrix_sync(&C[(size_t)(row0 + wm * 32 + i * 16) * M +
                                       col0 + wn * 32 + j * 16],
                                    acc[i][j], M, wmma::mem_row_major);
}

// ---------------- CSR build ---------------------------------------------------
__global__ void k_count(const int* __restrict__ dst, int E) {
    int e = blockIdx.x * blockDim.x + threadIdx.x;
    if (e < E) atomicAdd(&d_deg[dst[e]], 1);
}
__global__ void k_scan1(int N) {
    __shared__ int sm[SB];
    int i = blockIdx.x * SB + threadIdx.x;
    int v = (i < N) ? d_deg[i] : 0;
    sm[threadIdx.x] = v;
    __syncthreads();
    #pragma unroll
    for (int off = 1; off < SB; off <<= 1) {
        int t = (threadIdx.x >= off) ? sm[threadIdx.x - off] : 0;
        __syncthreads();
        sm[threadIdx.x] += t;
        __syncthreads();
    }
    if (i < N) d_rs[i] = sm[threadIdx.x] - v;
    if (threadIdx.x == SB - 1) d_bt[blockIdx.x] = sm[SB - 1];
}
__global__ void k_scan2(int nb) {
    if (threadIdx.x == 0) {
        int run = 0;
        for (int b = 0; b < nb; b++) { int t = d_bt[b]; d_bt[b] = run; run += t; }
    }
}
__global__ void k_scan3(int N, int E) {
    int i = blockIdx.x * SB + threadIdx.x;
    if (i < N) d_rs[i] += d_bt[blockIdx.x];
    if (i == 0) d_rs[N] = E;
}
__global__ void k_scatter(const int* __restrict__ src, const int* __restrict__ dst, int E) {
    int e = blockIdx.x * blockDim.x + threadIdx.x;
    if (e >= E) return;
    int d = dst[e];
    int pos = d_rs[d] + atomicAdd(&d_cur[d], 1);
    d_srcs[pos] = src[e];
}

// ---------------- layer1 node prep: al/ar dot-products + guidance -------------
__global__ void node_prep1(const float* __restrict__ x,
                           const float* __restrict__ attl,
                           const float* __restrict__ attr, int N) {
    int w = (blockIdx.x * blockDim.x + threadIdx.x) >> 5;
    int lane = threadIdx.x & 31;
    if (w >= N) return;
    const float* hrow = &d_h1[(size_t)w * 256];
    float aL[4] = {0.f, 0.f, 0.f, 0.f}, aR[4] = {0.f, 0.f, 0.f, 0.f};
    #pragma unroll
    for (int i = 0; i < 8; i++) {
        int idx = lane + i * 32;
        float hv = hrow[idx];
        int h = idx >> 6;
        aL[h] += hv * attl[idx];
        aR[h] += hv * attr[idx];
    }
    #pragma unroll
    for (int h = 0; h < 4; h++) {
        #pragma unroll
        for (int off = 16; off; off >>= 1) {
            aL[h] += __shfl_xor_sync(0xffffffffu, aL[h], off);
            aR[h] += __shfl_xor_sync(0xffffffffu, aR[h], off);
        }
    }
    if (lane == 0) {
        #pragma unroll
        for (int h = 0; h < 4; h++) {
            d_al1[w * 4 + h] = aL[h];
            d_ar1[w * 4 + h] = aR[h];
        }
        // L1-normalization constant of rw cancels in segment softmax -> drop it
        d_g1[w] = -0.1f * logf(fabsf(x[(size_t)w * 128 + 127]) + 1e-6f);
    }
}

// ---------------- layer1 CSR aggregation: warp per dst node -------------------
__global__ void agg1_csr(int N) {
    int n = (blockIdx.x * blockDim.x + threadIdx.x) >> 5;
    int lane = threadIdx.x & 31;
    if (n >= N) return;
    int beg = d_rs[n], end = d_rs[n + 1];
    float alh = (lane < 4) ? d_al1[n * 4 + lane] : 0.f;
    float4 accA = make_float4(0.f, 0.f, 0.f, 0.f);
    float4 accB = make_float4(0.f, 0.f, 0.f, 0.f);
    float wsum = 0.f;
    for (int p = beg; p < end; p++) {
        int s = d_srcs[p];
        float ex = 0.f;
        if (lane < 4) {
            float v = alh + d_ar1[s * 4 + lane];
            v = v > 0.f ? v : 0.01f * v;        // leaky relu
            v += d_g1[s];                       // guidance (shift-safe softmax)
            ex = __expf(v);
            wsum += ex;
        }
        float w0 = __shfl_sync(0xffffffffu, ex, 0);
        float w1 = __shfl_sync(0xffffffffu, ex, 1);
        float w2 = __shfl_sync(0xffffffffu, ex, 2);
        float w3 = __shfl_sync(0xffffffffu, ex, 3);
        float wa = (lane < 16) ? w0 : w1;
        float wb = (lane < 16) ? w2 : w3;
        const float4* hs = (const float4*)&d_h1[(size_t)s * 256];
        float4 a = hs[lane];
        float4 b = hs[lane + 32];
        accA.x += a.x * wa; accA.y += a.y * wa; accA.z += a.z * wa; accA.w += a.w * wa;
        accB.x += b.x * wb; accB.y += b.y * wb; accB.z += b.z * wb; accB.w += b.w * wb;
    }
    float s0 = __shfl_sync(0xffffffffu, wsum, 0);
    float s1 = __shfl_sync(0xffffffffu, wsum, 1);
    float s2 = __shfl_sync(0xffffffffu, wsum, 2);
    float s3 = __shfl_sync(0xffffffffu, wsum, 3);
    float inva = 1.f / (((lane < 16) ? s0 : s1) + 1e-16f);
    float invb = 1.f / (((lane < 16) ? s2 : s3) + 1e-16f);
    accA.x = elu_f(accA.x * inva); accA.y = elu_f(accA.y * inva);
    accA.z = elu_f(accA.z * inva); accA.w = elu_f(accA.w * inva);
    accB.x = elu_f(accB.x * invb); accB.y = elu_f(accB.y * invb);
    accB.z = elu_f(accB.z * invb); accB.w = elu_f(accB.w * invb);
    float* xr = &d_x2[(size_t)n * 256];
    *(float4*)&xr[lane * 4] = accA;
    *(float4*)&xr[128 + lane * 4] = accB;
    if (lane == 31)
        d_g2[n] = -0.1f * logf(fabsf(accB.w) + 1e-6f);
}

// ---------------- layer2 node prep --------------------------------------------
__global__ void node_prep2(const float* __restrict__ attl,
                           const float* __restrict__ attr, int N) {
    int w = (blockIdx.x * blockDim.x + threadIdx.x) >> 5;
    int lane = threadIdx.x & 31;
    if (w >= N) return;
    float aL = 0.f, aR = 0.f;
    #pragma unroll
    for (int i = 0; i < 2; i++) {
        int idx = lane + i * 32;
        float hv = d_h2[(size_t)w * 64 + idx];
        aL += hv * attl[idx];
        aR += hv * attr[idx];
    }
    #pragma unroll
    for (int off = 16; off; off >>= 1) {
        aL += __shfl_xor_sync(0xffffffffu, aL, off);
        aR += __shfl_xor_sync(0xffffffffu, aR, off);
    }
    if (lane == 0) { d_al2[w] = aL; d_ar2[w] = aR; }
}

// ---------------- layer2 CSR aggregation + normalize + ELU + final FC ---------
__global__ void agg2_csr(const float* __restrict__ fcw, const float* __restrict__ fcb,
                         float* __restrict__ out, int N) {
    int n = (blockIdx.x * blockDim.x + threadIdx.x) >> 5;
    int lane = threadIdx.x & 31;
    if (n >= N) return;
    int beg = d_rs[n], end = d_rs[n + 1];
    float aln = d_al2[n];
    float2 acc = make_float2(0.f, 0.f);
    float wsum = 0.f;
    for (int p = beg; p < end; p++) {
        int s = d_srcs[p];
        float ex = 0.f;
        if (lane == 0) {
            float v = aln + d_ar2[s];
            v = v > 0.f ? v : 0.01f * v;
            v += d_g2[s];
            ex = __expf(v);
            wsum += ex;
        }
        ex = __shfl_sync(0xffffffffu, ex, 0);
        float2 hv = ((const float2*)&d_h2[(size_t)s * 64])[lane];
        acc.x += hv.x * ex;
        acc.y += hv.y * ex;
    }
    wsum = __shfl_sync(0xffffffffu, wsum, 0);
    float inv = 1.f / (wsum + 1e-16f);
    float v0 = elu_f(acc.x * inv);
    float v1 = elu_f(acc.y * inv);
    float dot = v0 * fcw[2 * lane] + v1 * fcw[2 * lane + 1];
    #pragma unroll
    for (int off = 16; off; off >>= 1)
        dot += __shfl_xor_sync(0xffffffffu, dot, off);
    if (lane == 0) out[n] = dot + fcb[0];
}

// ---------------- host launcher ----------------------------------------------
extern "C" void kernel_launch(void* const* d_in, const int* in_sizes, int n_in,
                              void* d_out, int out_size) {
    const float* x     = (const float*)d_in[0];
    const int*   ei    = (const int*)d_in[1];
    const float* W1    = (const float*)d_in[2];
    const float* attl1 = (const float*)d_in[3];
    const float* attr1 = (const float*)d_in[4];
    const float* W2    = (const float*)d_in[5];
    const float* attl2 = (const float*)d_in[6];
    const float* attr2 = (const float*)d_in[7];
    const float* fcw   = (const float*)d_in[8];
    const float* fcb   = (const float*)d_in[9];
    float* out = (float*)d_out;

    int N = in_sizes[0] / 128;
    int E = in_sizes[1] / 2;
    const int* src = ei;
    const int* dst = ei + E;

    void *ph1, *ph2, *px2, *pdeg, *pcur;
    cudaGetSymbolAddress(&ph1, d_h1);
    cudaGetSymbolAddress(&ph2, d_h2);
    cudaGetSymbolAddress(&px2, d_x2);
    cudaGetSymbolAddress(&pdeg, d_deg);
    cudaGetSymbolAddress(&pcur, d_cur);

    const int TB = 256;
    int gy = (N + 127) / 128;
    int nb = (N + SB - 1) / SB;

    // ---- CSR build (dst-sorted edges) ----
    cudaMemsetAsync(pdeg, 0, sizeof(int) * (size_t)N, 0);
    cudaMemsetAsync(pcur, 0, sizeof(int) * (size_t)N, 0);
    k_count<<<(E + TB - 1) / TB, TB>>>(dst, E);
    k_scan1<<<nb, SB>>>(N);
    k_scan2<<<1, 32>>>(nb);
    k_scan3<<<nb, SB>>>(N, E);
    k_scatter<<<(E + TB - 1) / TB, TB>>>(src, dst, E);

    // ---- layer 1 ----
    gemm_tf32x3<<<dim3(4, gy), TB>>>(x, W1, (float*)ph1, N, 128, 256);
    node_prep1<<<(N * 32 + TB - 1) / TB, TB>>>(x, attl1, attr1, N);
    agg1_csr<<<(N * 32 + TB - 1) / TB, TB>>>(N);

    // ---- layer 2 ----
    gemm_tf32x3<<<dim3(1, gy), TB>>>((const float*)px2, W2, (float*)ph2, N, 256, 64);
    node_prep2<<<(N * 32 + TB - 1) / TB, TB>>>(attl2, attr2, N);
    agg2_csr<<<(N * 32 + TB - 1) / TB, TB>>>(fcw, fcb, out, N);
}

// round 7
// speedup vs baseline: 1.1340x; 1.1340x over previous
#include <cuda_runtime.h>
#include <math.h>

#define NMAX 50000
#define EMAX 800000
#define SB   512     // scan block size

// ---------------- scratch (device globals; no allocation allowed) ------------
__device__ float d_h1[NMAX * 256];   // layer1 transformed features
__device__ float d_al1[NMAX * 4];
__device__ float d_ar1[NMAX * 4];
__device__ float d_g1[NMAX];
__device__ float d_x2[NMAX * 256];   // elu(normalized aggregate) = GEMM2 input
__device__ float d_h2[NMAX * 64];
__device__ float d_al2[NMAX];
__device__ float d_ar2[NMAX];
__device__ float d_g2[NMAX];
// CSR (edges sorted by destination)
__device__ int   d_deg[NMAX];
__device__ int   d_cur[NMAX];
__device__ int   d_rs[NMAX + 1];
__device__ int   d_bt[(NMAX + SB - 1) / SB];
__device__ int   d_srcs[EMAX];

__device__ __forceinline__ float elu_f(float v) {
    return v > 0.f ? v : (__expf(v) - 1.0f);
}

// ---------------- fp32 SGEMM, 128xBN tile, BK=8, 8xTN microtile ---------------
// 256 threads (16x16). A stored K-transposed in smem. One-stage G->reg prefetch.
// FMA:LDS ratio 8:1 (TN=8) — FMA-pipe bound, ~2x the old 64x64 kernel.
template <int BN, int TN>
__global__ __launch_bounds__(256) void sgemm_opt(
        const float* __restrict__ A, const float* __restrict__ B,
        float* __restrict__ C, int N, int K, int M) {
    __shared__ float As[8][128];
    __shared__ float Bs[8][BN];
    const int tid = threadIdx.x;
    const int tx = tid & 15, ty = tid >> 4;
    const int row0 = blockIdx.y * 128, col0 = blockIdx.x * BN;
    // A tile load: 128x8 = 256 float4, 1/thread, stored transposed
    const int ar = tid >> 1, ac = (tid & 1) * 4;
    // B tile load: 8xBN = 2*BN float4
    const int bq = BN / 4;
    const int br = tid / bq, bc = (tid % bq) * 4;
    const bool bact = tid < 2 * BN;

    float4 aReg = make_float4(0.f, 0.f, 0.f, 0.f);
    float4 bReg = make_float4(0.f, 0.f, 0.f, 0.f);
    {
        int row = row0 + ar;
        if (row < N) aReg = *(const float4*)&A[(size_t)row * K + ac];
        if (bact)    bReg = *(const float4*)&B[(size_t)br * M + col0 + bc];
    }
    float acc[8][TN] = {};

    for (int k0 = 0; k0 < K; k0 += 8) {
        __syncthreads();
        As[ac + 0][ar] = aReg.x;
        As[ac + 1][ar] = aReg.y;
        As[ac + 2][ar] = aReg.z;
        As[ac + 3][ar] = aReg.w;
        if (bact) *(float4*)&Bs[br][bc] = bReg;
        __syncthreads();
        if (k0 + 8 < K) {                    // prefetch next tiles into regs
            int row = row0 + ar;
            aReg = make_float4(0.f, 0.f, 0.f, 0.f);
            if (row < N) aReg = *(const float4*)&A[(size_t)row * K + k0 + 8 + ac];
            if (bact)    bReg = *(const float4*)&B[(size_t)(k0 + 8 + br) * M + col0 + bc];
        }
        #pragma unroll
        for (int k = 0; k < 8; k++) {
            float a[8], b[TN];
            *(float4*)&a[0] = *(float4*)&As[k][ty * 8];
            *(float4*)&a[4] = *(float4*)&As[k][ty * 8 + 4];
            #pragma unroll
            for (int j = 0; j < TN; j += 4)
                *(float4*)&b[j] = *(float4*)&Bs[k][tx * TN + j];
            #pragma unroll
            for (int i = 0; i < 8; i++)
                #pragma unroll
                for (int j = 0; j < TN; j++)
                    acc[i][j] += a[i] * b[j];
        }
    }
    #pragma unroll
    for (int i = 0; i < 8; i++) {
        int row = row0 + ty * 8 + i;
        if (row < N) {
            #pragma unroll
            for (int j = 0; j < TN; j += 4)
                *(float4*)&C[(size_t)row * M + col0 + tx * TN + j] = *(float4*)&acc[i][j];
        }
    }
}

// ---------------- CSR build ---------------------------------------------------
__global__ void k_count(const int* __restrict__ dst, int E) {
    int e = blockIdx.x * blockDim.x + threadIdx.x;
    if (e < E) atomicAdd(&d_deg[dst[e]], 1);
}
__global__ void k_scan1(int N) {
    __shared__ int sm[SB];
    int i = blockIdx.x * SB + threadIdx.x;
    int v = (i < N) ? d_deg[i] : 0;
    sm[threadIdx.x] = v;
    __syncthreads();
    #pragma unroll
    for (int off = 1; off < SB; off <<= 1) {
        int t = (threadIdx.x >= off) ? sm[threadIdx.x - off] : 0;
        __syncthreads();
        sm[threadIdx.x] += t;
        __syncthreads();
    }
    if (i < N) d_rs[i] = sm[threadIdx.x] - v;
    if (threadIdx.x == SB - 1) d_bt[blockIdx.x] = sm[SB - 1];
}
__global__ void k_scan2(int nb) {
    if (threadIdx.x == 0) {
        int run = 0;
        for (int b = 0; b < nb; b++) { int t = d_bt[b]; d_bt[b] = run; run += t; }
    }
}
__global__ void k_scan3(int N, int E) {
    int i = blockIdx.x * SB + threadIdx.x;
    if (i < N) d_rs[i] += d_bt[blockIdx.x];
    if (i == 0) d_rs[N] = E;
}
__global__ void k_scatter(const int* __restrict__ src, const int* __restrict__ dst, int E) {
    int e = blockIdx.x * blockDim.x + threadIdx.x;
    if (e >= E) return;
    int d = dst[e];
    int pos = d_rs[d] + atomicAdd(&d_cur[d], 1);
    d_srcs[pos] = src[e];
}

// ---------------- layer1 node prep: al/ar dot-products + guidance -------------
__global__ void node_prep1(const float* __restrict__ x,
                           const float* __restrict__ attl,
                           const float* __restrict__ attr, int N) {
    int w = (blockIdx.x * blockDim.x + threadIdx.x) >> 5;
    int lane = threadIdx.x & 31;
    if (w >= N) return;
    const float* hrow = &d_h1[(size_t)w * 256];
    float aL[4] = {0.f, 0.f, 0.f, 0.f}, aR[4] = {0.f, 0.f, 0.f, 0.f};
    #pragma unroll
    for (int i = 0; i < 8; i++) {
        int idx = lane + i * 32;
        float hv = hrow[idx];
        int h = idx >> 6;
        aL[h] += hv * attl[idx];
        aR[h] += hv * attr[idx];
    }
    #pragma unroll
    for (int h = 0; h < 4; h++) {
        #pragma unroll
        for (int off = 16; off; off >>= 1) {
            aL[h] += __shfl_xor_sync(0xffffffffu, aL[h], off);
            aR[h] += __shfl_xor_sync(0xffffffffu, aR[h], off);
        }
    }
    if (lane == 0) {
        #pragma unroll
        for (int h = 0; h < 4; h++) {
            d_al1[w * 4 + h] = aL[h];
            d_ar1[w * 4 + h] = aR[h];
        }
        // L1-normalization constant of rw cancels in segment softmax -> drop it
        d_g1[w] = -0.1f * logf(fabsf(x[(size_t)w * 128 + 127]) + 1e-6f);
    }
}

// ---------------- layer1 CSR aggregation: warp per dst node -------------------
__global__ void agg1_csr(int N) {
    int n = (blockIdx.x * blockDim.x + threadIdx.x) >> 5;
    int lane = threadIdx.x & 31;
    if (n >= N) return;
    int beg = d_rs[n], end = d_rs[n + 1];
    float alh = (lane < 4) ? d_al1[n * 4 + lane] : 0.f;
    float4 accA = make_float4(0.f, 0.f, 0.f, 0.f);
    float4 accB = make_float4(0.f, 0.f, 0.f, 0.f);
    float wsum = 0.f;
    for (int p = beg; p < end; p++) {
        int s = d_srcs[p];
        float ex = 0.f;
        if (lane < 4) {
            float v = alh + d_ar1[s * 4 + lane];
            v = v > 0.f ? v : 0.01f * v;        // leaky relu
            v += d_g1[s];                       // guidance (shift-safe softmax)
            ex = __expf(v);
            wsum += ex;
        }
        float w0 = __shfl_sync(0xffffffffu, ex, 0);
        float w1 = __shfl_sync(0xffffffffu, ex, 1);
        float w2 = __shfl_sync(0xffffffffu, ex, 2);
        float w3 = __shfl_sync(0xffffffffu, ex, 3);
        float wa = (lane < 16) ? w0 : w1;
        float wb = (lane < 16) ? w2 : w3;
        const float4* hs = (const float4*)&d_h1[(size_t)s * 256];
        float4 a = hs[lane];
        float4 b = hs[lane + 32];
        accA.x += a.x * wa; accA.y += a.y * wa; accA.z += a.z * wa; accA.w += a.w * wa;
        accB.x += b.x * wb; accB.y += b.y * wb; accB.z += b.z * wb; accB.w += b.w * wb;
    }
    float s0 = __shfl_sync(0xffffffffu, wsum, 0);
    float s1 = __shfl_sync(0xffffffffu, wsum, 1);
    float s2 = __shfl_sync(0xffffffffu, wsum, 2);
    float s3 = __shfl_sync(0xffffffffu, wsum, 3);
    float inva = 1.f / (((lane < 16) ? s0 : s1) + 1e-16f);
    float invb = 1.f / (((lane < 16) ? s2 : s3) + 1e-16f);
    accA.x = elu_f(accA.x * inva); accA.y = elu_f(accA.y * inva);
    accA.z = elu_f(accA.z * inva); accA.w = elu_f(accA.w * inva);
    accB.x = elu_f(accB.x * invb); accB.y = elu_f(accB.y * invb);
    accB.z = elu_f(accB.z * invb); accB.w = elu_f(accB.w * invb);
    float* xr = &d_x2[(size_t)n * 256];
    *(float4*)&xr[lane * 4] = accA;
    *(float4*)&xr[128 + lane * 4] = accB;
    if (lane == 31)
        d_g2[n] = -0.1f * logf(fabsf(accB.w) + 1e-6f);
}

// ---------------- layer2 node prep --------------------------------------------
__global__ void node_prep2(const float* __restrict__ attl,
                           const float* __restrict__ attr, int N) {
    int w = (blockIdx.x * blockDim.x + threadIdx.x) >> 5;
    int lane = threadIdx.x & 31;
    if (w >= N) return;
    float aL = 0.f, aR = 0.f;
    #pragma unroll
    for (int i = 0; i < 2; i++) {
        int idx = lane + i * 32;
        float hv = d_h2[(size_t)w * 64 + idx];
        aL += hv * attl[idx];
        aR += hv * attr[idx];
    }
    #pragma unroll
    for (int off = 16; off; off >>= 1) {
        aL += __shfl_xor_sync(0xffffffffu, aL, off);
        aR += __shfl_xor_sync(0xffffffffu, aR, off);
    }
    if (lane == 0) { d_al2[w] = aL; d_ar2[w] = aR; }
}

// ---------------- layer2 CSR aggregation + normalize + ELU + final FC ---------
__global__ void agg2_csr(const float* __restrict__ fcw, const float* __restrict__ fcb,
                         float* __restrict__ out, int N) {
    int n = (blockIdx.x * blockDim.x + threadIdx.x) >> 5;
    int lane = threadIdx.x & 31;
    if (n >= N) return;
    int beg = d_rs[n], end = d_rs[n + 1];
    float aln = d_al2[n];
    float2 acc = make_float2(0.f, 0.f);
    float wsum = 0.f;
    for (int p = beg; p < end; p++) {
        int s = d_srcs[p];
        float ex = 0.f;
        if (lane == 0) {
            float v = aln + d_ar2[s];
            v = v > 0.f ? v : 0.01f * v;
            v += d_g2[s];
            ex = __expf(v);
            wsum += ex;
        }
        ex = __shfl_sync(0xffffffffu, ex, 0);
        float2 hv = ((const float2*)&d_h2[(size_t)s * 64])[lane];
        acc.x += hv.x * ex;
        acc.y += hv.y * ex;
    }
    wsum = __shfl_sync(0xffffffffu, wsum, 0);
    float inv = 1.f / (wsum + 1e-16f);
    float v0 = elu_f(acc.x * inv);
    float v1 = elu_f(acc.y * inv);
    float dot = v0 * fcw[2 * lane] + v1 * fcw[2 * lane + 1];
    #pragma unroll
    for (int off = 16; off; off >>= 1)
        dot += __shfl_xor_sync(0xffffffffu, dot, off);
    if (lane == 0) out[n] = dot + fcb[0];
}

// ---------------- host launcher ----------------------------------------------
extern "C" void kernel_launch(void* const* d_in, const int* in_sizes, int n_in,
                              void* d_out, int out_size) {
    const float* x     = (const float*)d_in[0];
    const int*   ei    = (const int*)d_in[1];
    const float* W1    = (const float*)d_in[2];
    const float* attl1 = (const float*)d_in[3];
    const float* attr1 = (const float*)d_in[4];
    const float* W2    = (const float*)d_in[5];
    const float* attl2 = (const float*)d_in[6];
    const float* attr2 = (const float*)d_in[7];
    const float* fcw   = (const float*)d_in[8];
    const float* fcb   = (const float*)d_in[9];
    float* out = (float*)d_out;

    int N = in_sizes[0] / 128;
    int E = in_sizes[1] / 2;
    const int* src = ei;
    const int* dst = ei + E;

    void *ph1, *ph2, *px2, *pdeg, *pcur;
    cudaGetSymbolAddress(&ph1, d_h1);
    cudaGetSymbolAddress(&ph2, d_h2);
    cudaGetSymbolAddress(&px2, d_x2);
    cudaGetSymbolAddress(&pdeg, d_deg);
    cudaGetSymbolAddress(&pcur, d_cur);

    const int TB = 256;
    int gy = (N + 127) / 128;
    int nb = (N + SB - 1) / SB;

    // ---- CSR build (dst-sorted edges) ----
    cudaMemsetAsync(pdeg, 0, sizeof(int) * (size_t)N, 0);
    cudaMemsetAsync(pcur, 0, sizeof(int) * (size_t)N, 0);
    k_count<<<(E + TB - 1) / TB, TB>>>(dst, E);
    k_scan1<<<nb, SB>>>(N);
    k_scan2<<<1, 32>>>(nb);
    k_scan3<<<nb, SB>>>(N, E);
    k_scatter<<<(E + TB - 1) / TB, TB>>>(src, dst, E);

    // ---- layer 1 ----
    sgemm_opt<128, 8><<<dim3(2, gy), TB>>>(x, W1, (float*)ph1, N, 128, 256);
    node_prep1<<<(N * 32 + TB - 1) / TB, TB>>>(x, attl1, attr1, N);
    agg1_csr<<<(N * 32 + TB - 1) / TB, TB>>>(N);

    // ---- layer 2 ----
    sgemm_opt<64, 4><<<dim3(1, gy), TB>>>((const float*)px2, W2, (float*)ph2, N, 256, 64);
    node_prep2<<<(N * 32 + TB - 1) / TB, TB>>>(attl2, attr2, N);
    agg2_csr<<<(N * 32 + TB - 1) / TB, TB>>>(fcw, fcb, out, N);
}

// round 8
// speedup vs baseline: 1.3025x; 1.1486x over previous
#include <cuda_runtime.h>
#include <math.h>

#define NMAX 50000
#define EMAX 800000
#define SB   512     // scan block size

// ---------------- scratch (device globals; no allocation allowed) ------------
__device__ float d_h1[NMAX * 256];   // layer1 transformed features
__device__ float d_al1[NMAX * 4];
__device__ float d_ar1[NMAX * 4];
__device__ float d_g1[NMAX];
__device__ float d_x2[NMAX * 256];   // elu(normalized aggregate) = GEMM2 input
__device__ float d_h2[NMAX * 64];
__device__ float d_al2[NMAX];
__device__ float d_ar2[NMAX];
__device__ float d_g2[NMAX];
// CSR (edges sorted by destination)
__device__ int   d_deg[NMAX];
__device__ int   d_cur[NMAX];
__device__ int   d_rs[NMAX + 1];
__device__ int   d_bt[(NMAX + SB - 1) / SB];
__device__ int   d_srcs[EMAX];

__device__ __forceinline__ float elu_f(float v) {
    return v > 0.f ? v : (__expf(v) - 1.0f);
}

// ---------------- fp32 tiled SGEMM + fused attention epilogue -----------------
// C[N,M] = A[N,K] @ B[K,M]; 64x64 tile, BK=32, 256 threads, 4x4 microtile.
// Epilogue: each 64-col tile aligns with one attention head (64 ch/head), so the
// block holds the COMPLETE per-head dot products with att_l/att_r for its rows:
//   alout[row*HS + (col0>>6)] = sum_c C[row][col0+c]*attl[col0+c]  (HS=heads)
// computed by a 16-lane shfl reduction — kills the separate node_prep pass.
template <int HS>
__global__ __launch_bounds__(256) void sgemm64(
        const float* __restrict__ A, const float* __restrict__ B,
        float* __restrict__ C, int N, int K, int M,
        const float* __restrict__ attl, const float* __restrict__ attr,
        float* __restrict__ alout, float* __restrict__ arout) {
    __shared__ float As[64][33];
    __shared__ float Bs[32][64];
    int tx = threadIdx.x & 15;
    int ty = threadIdx.x >> 4;
    int row0 = blockIdx.y * 64;
    int col0 = blockIdx.x * 64;
    float acc[4][4] = {};
    for (int k0 = 0; k0 < K; k0 += 32) {
        #pragma unroll
        for (int i = 0; i < 2; i++) {
            int idx = threadIdx.x + i * 256;
            int r = idx >> 3;
            int c = (idx & 7) * 4;
            int row = row0 + r;
            float4 v = make_float4(0.f, 0.f, 0.f, 0.f);
            if (row < N) v = *(const float4*)&A[(size_t)row * K + k0 + c];
            As[r][c] = v.x; As[r][c + 1] = v.y; As[r][c + 2] = v.z; As[r][c + 3] = v.w;
        }
        #pragma unroll
        for (int i = 0; i < 2; i++) {
            int idx = threadIdx.x + i * 256;
            int r = idx >> 4;
            int c = (idx & 15) * 4;
            *(float4*)&Bs[r][c] = *(const float4*)&B[(size_t)(k0 + r) * M + col0 + c];
        }
        __syncthreads();
        #pragma unroll
        for (int k = 0; k < 32; k++) {
            float a[4], b[4];
            #pragma unroll
            for (int i = 0; i < 4; i++) a[i] = As[ty * 4 + i][k];
            #pragma unroll
            for (int j = 0; j < 4; j++) b[j] = Bs[k][tx * 4 + j];
            #pragma unroll
            for (int i = 0; i < 4; i++)
                #pragma unroll
                for (int j = 0; j < 4; j++)
                    acc[i][j] += a[i] * b[j];
        }
        __syncthreads();
    }
    #pragma unroll
    for (int i = 0; i < 4; i++) {
        int r = row0 + ty * 4 + i;
        if (r < N) {
            #pragma unroll
            for (int j = 0; j < 4; j++)
                C[(size_t)r * M + col0 + tx * 4 + j] = acc[i][j];
        }
    }
    // fused attention-dot epilogue
    float lv[4], rv[4];
    #pragma unroll
    for (int j = 0; j < 4; j++) {
        lv[j] = attl[col0 + tx * 4 + j];
        rv[j] = attr[col0 + tx * 4 + j];
    }
    float pal[4], par[4];
    #pragma unroll
    for (int i = 0; i < 4; i++) {
        float sl = 0.f, sr = 0.f;
        #pragma unroll
        for (int j = 0; j < 4; j++) {
            sl += acc[i][j] * lv[j];
            sr += acc[i][j] * rv[j];
        }
        pal[i] = sl; par[i] = sr;
    }
    #pragma unroll
    for (int off = 1; off < 16; off <<= 1) {
        #pragma unroll
        for (int i = 0; i < 4; i++) {
            pal[i] += __shfl_xor_sync(0xffffffffu, pal[i], off);
            par[i] += __shfl_xor_sync(0xffffffffu, par[i], off);
        }
    }
    if (tx == 0) {
        int h = col0 >> 6;
        #pragma unroll
        for (int i = 0; i < 4; i++) {
            int r = row0 + ty * 4 + i;
            if (r < N) {
                alout[r * HS + h] = pal[i];
                arout[r * HS + h] = par[i];
            }
        }
    }
}

// ---------------- CSR build ---------------------------------------------------
__global__ void k_count(const int* __restrict__ dst, int E) {
    int e = blockIdx.x * blockDim.x + threadIdx.x;
    if (e < E) atomicAdd(&d_deg[dst[e]], 1);
}
__global__ void k_scan1(int N) {
    __shared__ int sm[SB];
    int i = blockIdx.x * SB + threadIdx.x;
    int v = (i < N) ? d_deg[i] : 0;
    sm[threadIdx.x] = v;
    __syncthreads();
    #pragma unroll
    for (int off = 1; off < SB; off <<= 1) {
        int t = (threadIdx.x >= off) ? sm[threadIdx.x - off] : 0;
        __syncthreads();
        sm[threadIdx.x] += t;
        __syncthreads();
    }
    if (i < N) d_rs[i] = sm[threadIdx.x] - v;
    if (threadIdx.x == SB - 1) d_bt[blockIdx.x] = sm[SB - 1];
}
// scan2+scan3 merged: each block reduces d_bt[0..blockIdx) itself
__global__ void k_scan23(int N, int E) {
    __shared__ int soff;
    if (threadIdx.x == 0) soff = 0;
    __syncthreads();
    int v = (threadIdx.x < blockIdx.x) ? d_bt[threadIdx.x] : 0;
    #pragma unroll
    for (int off = 16; off; off >>= 1)
        v += __shfl_xor_sync(0xffffffffu, v, off);
    if ((threadIdx.x & 31) == 0 && v) atomicAdd(&soff, v);
    __syncthreads();
    int i = blockIdx.x * SB + threadIdx.x;
    if (i < N) d_rs[i] += soff;
    if (i == 0) d_rs[N] = E;
}
__global__ void k_scatter(const int* __restrict__ src, const int* __restrict__ dst, int E) {
    int e = blockIdx.x * blockDim.x + threadIdx.x;
    if (e >= E) return;
    int d = dst[e];
    int pos = d_rs[d] + atomicAdd(&d_cur[d], 1);
    d_srcs[pos] = src[e];
}

// ---------------- layer1 guidance from raw x ----------------------------------
__global__ void k_g1(const float* __restrict__ x, int N) {
    int i = blockIdx.x * blockDim.x + threadIdx.x;
    if (i < N)
        d_g1[i] = -0.1f * logf(fabsf(x[(size_t)i * 128 + 127]) + 1e-6f);
}

// ---------------- layer1 CSR aggregation: warp per dst node -------------------
__global__ void agg1_csr(int N) {
    int n = (blockIdx.x * blockDim.x + threadIdx.x) >> 5;
    int lane = threadIdx.x & 31;
    if (n >= N) return;
    int beg = d_rs[n], end = d_rs[n + 1];
    float alh = (lane < 4) ? d_al1[n * 4 + lane] : 0.f;
    float4 accA = make_float4(0.f, 0.f, 0.f, 0.f);
    float4 accB = make_float4(0.f, 0.f, 0.f, 0.f);
    float wsum = 0.f;
    for (int p = beg; p < end; p++) {
        int s = d_srcs[p];
        float ex = 0.f;
        if (lane < 4) {
            float v = alh + d_ar1[s * 4 + lane];
            v = v > 0.f ? v : 0.01f * v;        // leaky relu
            v += d_g1[s];                       // guidance (shift-safe softmax)
            ex = __expf(v);
            wsum += ex;
        }
        float w0 = __shfl_sync(0xffffffffu, ex, 0);
        float w1 = __shfl_sync(0xffffffffu, ex, 1);
        float w2 = __shfl_sync(0xffffffffu, ex, 2);
        float w3 = __shfl_sync(0xffffffffu, ex, 3);
        float wa = (lane < 16) ? w0 : w1;
        float wb = (lane < 16) ? w2 : w3;
        const float4* hs = (const float4*)&d_h1[(size_t)s * 256];
        float4 a = hs[lane];
        float4 b = hs[lane + 32];
        accA.x += a.x * wa; accA.y += a.y * wa; accA.z += a.z * wa; accA.w += a.w * wa;
        accB.x += b.x * wb; accB.y += b.y * wb; accB.z += b.z * wb; accB.w += b.w * wb;
    }
    float s0 = __shfl_sync(0xffffffffu, wsum, 0);
    float s1 = __shfl_sync(0xffffffffu, wsum, 1);
    float s2 = __shfl_sync(0xffffffffu, wsum, 2);
    float s3 = __shfl_sync(0xffffffffu, wsum, 3);
    float inva = 1.f / (((lane < 16) ? s0 : s1) + 1e-16f);
    float invb = 1.f / (((lane < 16) ? s2 : s3) + 1e-16f);
    accA.x = elu_f(accA.x * inva); accA.y = elu_f(accA.y * inva);
    accA.z = elu_f(accA.z * inva); accA.w = elu_f(accA.w * inva);
    accB.x = elu_f(accB.x * invb); accB.y = elu_f(accB.y * invb);
    accB.z = elu_f(accB.z * invb); accB.w = elu_f(accB.w * invb);
    float* xr = &d_x2[(size_t)n * 256];
    *(float4*)&xr[lane * 4] = accA;
    *(float4*)&xr[128 + lane * 4] = accB;
    if (lane == 31)
        d_g2[n] = -0.1f * logf(fabsf(accB.w) + 1e-6f);
}

// ---------------- layer2 CSR aggregation + normalize + ELU + final FC ---------
__global__ void agg2_csr(const float* __restrict__ fcw, const float* __restrict__ fcb,
                         float* __restrict__ out, int N) {
    int n = (blockIdx.x * blockDim.x + threadIdx.x) >> 5;
    int lane = threadIdx.x & 31;
    if (n >= N) return;
    int beg = d_rs[n], end = d_rs[n + 1];
    float aln = d_al2[n];
    float2 acc = make_float2(0.f, 0.f);
    float wsum = 0.f;
    for (int p = beg; p < end; p++) {
        int s = d_srcs[p];
        float ex = 0.f;
        if (lane == 0) {
            float v = aln + d_ar2[s];
            v = v > 0.f ? v : 0.01f * v;
            v += d_g2[s];
            ex = __expf(v);
            wsum += ex;
        }
        ex = __shfl_sync(0xffffffffu, ex, 0);
        float2 hv = ((const float2*)&d_h2[(size_t)s * 64])[lane];
        acc.x += hv.x * ex;
        acc.y += hv.y * ex;
    }
    wsum = __shfl_sync(0xffffffffu, wsum, 0);
    float inv = 1.f / (wsum + 1e-16f);
    float v0 = elu_f(acc.x * inv);
    float v1 = elu_f(acc.y * inv);
    float dot = v0 * fcw[2 * lane] + v1 * fcw[2 * lane + 1];
    #pragma unroll
    for (int off = 16; off; off >>= 1)
        dot += __shfl_xor_sync(0xffffffffu, dot, off);
    if (lane == 0) out[n] = dot + fcb[0];
}

// ---------------- host launcher ----------------------------------------------
extern "C" void kernel_launch(void* const* d_in, const int* in_sizes, int n_in,
                              void* d_out, int out_size) {
    const float* x     = (const float*)d_in[0];
    const int*   ei    = (const int*)d_in[1];
    const float* W1    = (const float*)d_in[2];
    const float* attl1 = (const float*)d_in[3];
    const float* attr1 = (const float*)d_in[4];
    const float* W2    = (const float*)d_in[5];
    const float* attl2 = (const float*)d_in[6];
    const float* attr2 = (const float*)d_in[7];
    const float* fcw   = (const float*)d_in[8];
    const float* fcb   = (const float*)d_in[9];
    float* out = (float*)d_out;

    int N = in_sizes[0] / 128;
    int E = in_sizes[1] / 2;
    const int* src = ei;
    const int* dst = ei + E;

    void *ph1, *ph2, *px2, *pdeg, *pcur;
    void *pal1, *par1, *pal2, *par2;
    cudaGetSymbolAddress(&ph1, d_h1);
    cudaGetSymbolAddress(&ph2, d_h2);
    cudaGetSymbolAddress(&px2, d_x2);
    cudaGetSymbolAddress(&pdeg, d_deg);
    cudaGetSymbolAddress(&pcur, d_cur);
    cudaGetSymbolAddress(&pal1, d_al1);
    cudaGetSymbolAddress(&par1, d_ar1);
    cudaGetSymbolAddress(&pal2, d_al2);
    cudaGetSymbolAddress(&par2, d_ar2);

    const int TB = 256;
    int gy = (N + 63) / 64;
    int nb = (N + SB - 1) / SB;

    // launch order fixed so launch index 5 (ncu -s 5 -c 1) == gemm1
    cudaMemsetAsync(pdeg, 0, sizeof(int) * (size_t)N, 0);              // 0
    cudaMemsetAsync(pcur, 0, sizeof(int) * (size_t)N, 0);              // 1
    k_count<<<(E + TB - 1) / TB, TB>>>(dst, E);                        // 2
    k_scan1<<<nb, SB>>>(N);                                            // 3
    k_scan23<<<nb, SB>>>(N, E);                                        // 4
    sgemm64<4><<<dim3(4, gy), TB>>>(x, W1, (float*)ph1, N, 128, 256,   // 5
                                    attl1, attr1, (float*)pal1, (float*)par1);
    k_scatter<<<(E + TB - 1) / TB, TB>>>(src, dst, E);                 // 6
    k_g1<<<(N + TB - 1) / TB, TB>>>(x, N);                             // 7
    agg1_csr<<<(N * 32 + TB - 1) / TB, TB>>>(N);                       // 8
    sgemm64<1><<<dim3(1, gy), TB>>>((const float*)px2, W2, (float*)ph2, // 9
                                    N, 256, 64, attl2, attr2,
                                    (float*)pal2, (float*)par2);
    agg2_csr<<<(N * 32 + TB - 1) / TB, TB>>>(fcw, fcb, out, N);        // 10
}